// round 8
// baseline (speedup 1.0000x reference)
#include <cuda_runtime.h>
#include <math.h>

// x: (16, 10, 512, 512) f32. out: (16, 8, 512, 512) f32.
// Per pixel: mag = sqrt(x[8]^2 + x[9]^2); k = argmax over x[0..7] (first max);
// out[c] = (c==k) ? mag : 0.
//
// 256-bit (v8) global accesses: each thread handles 8 consecutive pixels.
// One warp instruction touches 8KB contiguous -> half the L1tex wavefronts,
// longer same-direction DRAM bursts. Stores remain write-through (best R7).

#define CH_ELEMS 262144              // 512*512 floats per channel
#define PIX_PER_THREAD 8
#define VECS_PER_BATCH (CH_ELEMS / PIX_PER_THREAD)   // 32768
#define NBATCH 16
#define TOTAL_THREADS (NBATCH * VECS_PER_BATCH)      // 524,288

__device__ __forceinline__ void ldg256(const float* p, float r[8]) {
    asm volatile("ld.global.v8.f32 {%0,%1,%2,%3,%4,%5,%6,%7}, [%8];"
        : "=f"(r[0]), "=f"(r[1]), "=f"(r[2]), "=f"(r[3]),
          "=f"(r[4]), "=f"(r[5]), "=f"(r[6]), "=f"(r[7])
        : "l"(p));
}

__device__ __forceinline__ void stg256_wt(float* p, const float r[8]) {
    asm volatile("st.global.wt.v8.f32 [%0], {%1,%2,%3,%4,%5,%6,%7,%8};"
        :: "l"(p),
           "f"(r[0]), "f"(r[1]), "f"(r[2]), "f"(r[3]),
           "f"(r[4]), "f"(r[5]), "f"(r[6]), "f"(r[7])
        : "memory");
}

__global__ __launch_bounds__(256) void histogram_layer_kernel(
    const float* __restrict__ x, float* __restrict__ out)
{
    int i = blockIdx.x * blockDim.x + threadIdx.x;  // grid exact, no guard

    int b = i >> 15;               // i / VECS_PER_BATCH
    int p = (i & (VECS_PER_BATCH - 1)) * PIX_PER_THREAD;

    const float* in_base = x + (size_t)b * 10 * CH_ELEMS + p;

    // Ten 256-bit loads (8 cosines + 2 grads), front-batched.
    float c[8][8];
#pragma unroll
    for (int k = 0; k < 8; k++) ldg256(in_base + (size_t)k * CH_ELEMS, c[k]);
    float g0[8], g1[8];
    ldg256(in_base + (size_t)8 * CH_ELEMS, g0);
    ldg256(in_base + (size_t)9 * CH_ELEMS, g1);

    // Per-pixel argmax (strict > keeps lowest index on ties, like jnp.argmax)
    int idx[8];
    float mag[8];
#pragma unroll
    for (int j = 0; j < 8; j++) {
        float best = c[0][j];
        int bi = 0;
#pragma unroll
        for (int k = 1; k < 8; k++) {
            if (c[k][j] > best) { best = c[k][j]; bi = k; }
        }
        idx[j] = bi;
        mag[j] = sqrtf(g0[j] * g0[j] + g1[j] * g1[j]);
    }

    float* out_base = out + (size_t)b * 8 * CH_ELEMS + p;
#pragma unroll
    for (int k = 0; k < 8; k++) {
        float o[8];
#pragma unroll
        for (int j = 0; j < 8; j++) o[j] = (idx[j] == k) ? mag[j] : 0.0f;
        stg256_wt(out_base + (size_t)k * CH_ELEMS, o);
    }
}

extern "C" void kernel_launch(void* const* d_in, const int* in_sizes, int n_in,
                              void* d_out, int out_size)
{
    const float* x = (const float*)d_in[0];
    float* out = (float*)d_out;
    histogram_layer_kernel<<<TOTAL_THREADS / 256, 256>>>(x, out);
}

// round 9
// speedup vs baseline: 1.0006x; 1.0006x over previous
#include <cuda_runtime.h>
#include <math.h>

// x: (16, 10, 512, 512) f32. out: (16, 8, 512, 512) f32.
// Per pixel: mag = sqrt(x[8]^2 + x[9]^2); k = argmax over x[0..7] (first max);
// out[c] = (c==k) ? mag : 0.
//
// 256-bit (v8) global accesses, 8 pixels/thread, write-through stores.
// 128-thread blocks: 5 CTAs/SM at 92 regs -> 20 warps/SM and a finer-grained
// tail wave than 256-thread blocks (2 CTAs/SM).

#define CH_ELEMS 262144              // 512*512 floats per channel
#define PIX_PER_THREAD 8
#define VECS_PER_BATCH (CH_ELEMS / PIX_PER_THREAD)   // 32768
#define NBATCH 16
#define TOTAL_THREADS (NBATCH * VECS_PER_BATCH)      // 524,288

__device__ __forceinline__ void ldg256(const float* p, float r[8]) {
    asm volatile("ld.global.v8.f32 {%0,%1,%2,%3,%4,%5,%6,%7}, [%8];"
        : "=f"(r[0]), "=f"(r[1]), "=f"(r[2]), "=f"(r[3]),
          "=f"(r[4]), "=f"(r[5]), "=f"(r[6]), "=f"(r[7])
        : "l"(p));
}

__device__ __forceinline__ void stg256_wt(float* p, const float r[8]) {
    asm volatile("st.global.wt.v8.f32 [%0], {%1,%2,%3,%4,%5,%6,%7,%8};"
        :: "l"(p),
           "f"(r[0]), "f"(r[1]), "f"(r[2]), "f"(r[3]),
           "f"(r[4]), "f"(r[5]), "f"(r[6]), "f"(r[7])
        : "memory");
}

__global__ __launch_bounds__(128, 5) void histogram_layer_kernel(
    const float* __restrict__ x, float* __restrict__ out)
{
    int i = blockIdx.x * blockDim.x + threadIdx.x;  // grid exact, no guard

    int b = i >> 15;               // i / VECS_PER_BATCH
    int p = (i & (VECS_PER_BATCH - 1)) * PIX_PER_THREAD;

    const float* in_base = x + (size_t)b * 10 * CH_ELEMS + p;

    // Ten 256-bit loads (8 cosines + 2 grads), front-batched.
    float c[8][8];
#pragma unroll
    for (int k = 0; k < 8; k++) ldg256(in_base + (size_t)k * CH_ELEMS, c[k]);
    float g0[8], g1[8];
    ldg256(in_base + (size_t)8 * CH_ELEMS, g0);
    ldg256(in_base + (size_t)9 * CH_ELEMS, g1);

    // Per-pixel argmax (strict > keeps lowest index on ties, like jnp.argmax)
    int idx[8];
    float mag[8];
#pragma unroll
    for (int j = 0; j < 8; j++) {
        float best = c[0][j];
        int bi = 0;
#pragma unroll
        for (int k = 1; k < 8; k++) {
            if (c[k][j] > best) { best = c[k][j]; bi = k; }
        }
        idx[j] = bi;
        mag[j] = sqrtf(g0[j] * g0[j] + g1[j] * g1[j]);
    }

    float* out_base = out + (size_t)b * 8 * CH_ELEMS + p;
#pragma unroll
    for (int k = 0; k < 8; k++) {
        float o[8];
#pragma unroll
        for (int j = 0; j < 8; j++) o[j] = (idx[j] == k) ? mag[j] : 0.0f;
        stg256_wt(out_base + (size_t)k * CH_ELEMS, o);
    }
}

extern "C" void kernel_launch(void* const* d_in, const int* in_sizes, int n_in,
                              void* d_out, int out_size)
{
    const float* x = (const float*)d_in[0];
    float* out = (float*)d_out;
    histogram_layer_kernel<<<TOTAL_THREADS / 128, 128>>>(x, out);
}